// round 9
// baseline (speedup 1.0000x reference)
#include <cuda_runtime.h>
#include <math.h>

#define HH 64
#define WW 64
#define NUM_POS 48
#define CC 384
#define BB 32
#define ST 64             // hrow tile stride (floats); 66 rows x 64 cols

struct __align__(16) PosParam {
    float wx0, wx1, wx2;
    float wy0, wy1, wy2;
    int   ox, oy;
};

__device__ PosParam g_pp[NUM_POS];

// ---- tiny LUT kernel: separable normalized Gaussian weights per position ----
__global__ void precompute_weights(const float* __restrict__ offset)
{
    const int p = threadIdx.x;
    if (p >= NUM_POS) return;
    const float offx = offset[p * 2 + 0];
    const float offy = offset[p * 2 + 1];
    const float rx = rintf(offx);                 // == iw*16 exactly (jitter < 0.5)
    const float ry = rintf(offy);
    const float fx = offx - rx;
    const float fy = offy - ry;

    float gx[3], gy[3], sx = 0.f, sy = 0.f;
    #pragma unroll
    for (int k = 0; k < 3; k++) {
        const float dx = (float)(k - 1) + fx;
        const float dy = (float)(k - 1) + fy;
        gx[k] = expf(-2.0f * dx * dx);            // sigma = 0.5
        gy[k] = expf(-2.0f * dy * dy);
        sx += gx[k];
        sy += gy[k];
    }
    const float ix = 1.0f / sx, iy = 1.0f / sy;   // normalizer factors (separable)
    PosParam pp;
    pp.wx0 = gx[0] * ix; pp.wx1 = gx[1] * ix; pp.wx2 = gx[2] * ix;
    pp.wy0 = gy[0] * iy; pp.wy1 = gy[1] * iy; pp.wy2 = gy[2] * iy;
    pp.ox = (int)rx;     pp.oy = (int)ry;
    g_pp[p] = pp;
}

// ---- main fused kernel: displace + separable 3x3 Gaussian ----
// smem holds HORIZONTALLY-CONVOLVED rows: hrow[t][x], t = displaced_y + 1.
// Rows t=0 and t=65 (displaced y = -1, 64) are always zero.
__global__ __launch_bounds__(256, 8)
void displace_gauss_kernel(const float* __restrict__ inp,
                           float* __restrict__ out)
{
    __shared__ float hrow[66 * ST];

    const int c = blockIdx.x;
    const int b = blockIdx.y;
    const int tid = threadIdx.x;

    const PosParam pp = g_pp[c >> 3];
    const int ox = pp.ox, oy = pp.oy;  // multiples of 16 by construction

    // --- zero rows t=0 and t=65 (32 STS.128 total) ---
    if (tid < 32) {
        const int t  = (tid < 16) ? 0 : 65;
        const int c4 = (tid & 15) << 2;
        *(float4*)&hrow[t * ST + c4] = make_float4(0.f, 0.f, 0.f, 0.f);
    }

    // --- fill: load displaced row chunk, hconv via shuffles, store hconv'd ---
    const float* __restrict__ src = inp + ((size_t)b * CC + c) * (HH * WW);
    const int cg    = tid & 15;        // column group: cols x4..x4+3
    const int x4    = cg << 2;
    const int sx    = x4 - ox;         // aligned: ox % 16 == 0
    const bool okx  = (unsigned)sx < (unsigned)WW;
    const int ybase = tid >> 4;

    const float wx0 = pp.wx0, wx1 = pp.wx1, wx2 = pp.wx2;

    #pragma unroll
    for (int k = 0; k < 4; k++) {
        const int y  = ybase + k * 16;     // displaced row 0..63
        const int sy = y - oy;
        float4 v = make_float4(0.f, 0.f, 0.f, 0.f);
        if (okx && (unsigned)sy < (unsigned)HH)
            v = *(const float4*)(src + sy * WW + sx);

        // neighbors via shuffle; a neighbor float4 that was masked-out shuffles
        // in as 0 (correct), and cols -1 / 64 are forced 0 at cg edges.
        float lf = __shfl_up_sync(0xffffffffu, v.w, 1);
        float rt = __shfl_down_sync(0xffffffffu, v.x, 1);
        if (cg == 0)  lf = 0.f;
        if (cg == 15) rt = 0.f;

        float4 h;
        h.x = fmaf(wx0, lf,  fmaf(wx1, v.x, wx2 * v.y));
        h.y = fmaf(wx0, v.x, fmaf(wx1, v.y, wx2 * v.z));
        h.z = fmaf(wx0, v.y, fmaf(wx1, v.z, wx2 * v.w));
        h.w = fmaf(wx0, v.z, fmaf(wx1, v.w, wx2 * rt));
        *(float4*)&hrow[(y + 1) * ST + x4] = h;
    }
    __syncthreads();

    // --- vconv: 4-col x 4-row patch per thread, rolling 3 hrows in regs ---
    const int strip = tid >> 4;
    const int y0 = strip << 2;
    const float wy0 = pp.wy0, wy1 = pp.wy1, wy2 = pp.wy2;

    float* __restrict__ dst = out + ((size_t)b * CC + c) * (HH * WW);

    float4 h0 = *(const float4*)&hrow[(y0 + 0) * ST + x4];  // displaced y0-1
    float4 h1 = *(const float4*)&hrow[(y0 + 1) * ST + x4];  // displaced y0
    #pragma unroll
    for (int r = 0; r < 4; r++) {
        const float4 hn = *(const float4*)&hrow[(y0 + 2 + r) * ST + x4];
        float4 o;
        o.x = fmaf(wy0, h0.x, fmaf(wy1, h1.x, wy2 * hn.x));
        o.y = fmaf(wy0, h0.y, fmaf(wy1, h1.y, wy2 * hn.y));
        o.z = fmaf(wy0, h0.z, fmaf(wy1, h1.z, wy2 * hn.z));
        o.w = fmaf(wy0, h0.w, fmaf(wy1, h1.w, wy2 * hn.w));
        *(float4*)&dst[(y0 + r) * WW + x4] = o;
        h0 = h1;
        h1 = hn;
    }
}

extern "C" void kernel_launch(void* const* d_in, const int* in_sizes, int n_in,
                              void* d_out, int out_size)
{
    const float* inp    = (const float*)d_in[0];   // (32, 384, 64, 64) fp32
    const float* offset = (const float*)d_in[1];   // (48, 2) fp32
    float* out          = (float*)d_out;           // (32, 384, 64, 64) fp32

    precompute_weights<<<1, 64>>>(offset);
    dim3 grid(CC, BB);   // one CTA per (b, c) plane
    displace_gauss_kernel<<<grid, 256>>>(inp, out);
}